// round 16
// baseline (speedup 1.0000x reference)
#include <cuda_runtime.h>
#include <cstdint>

// Problem constants (fixed shapes)
#define T_LEN 512
#define B_SZ  256
#define C_SZ  4
#define K_SZ  64
#define L2E   1.4426950408889634f
#define LN2   0.6931471805599453f

#define N_CHAIN (B_SZ * C_SZ)                // 1024
#define TSTR2   ((B_SZ * C_SZ * K_SZ) / 2)   // time stride in float2 units

// Scratch for the forward/backward meet (allocation-free rule: device globals)
__device__ float g_vec[2 * N_CHAIN][K_SZ];   // [2*chain + dir][state]
__device__ float g_m2 [2 * N_CHAIN];         // log2 offsets
__device__ float g_np [2 * N_CHAIN];         // numerator partials (per dir)
__device__ int   g_flag[N_CHAIN];            // completion counters (zero-init)

// ---------- small PTX helpers ----------
static __device__ __forceinline__ float ex2f(float x) {
    float y; asm("ex2.approx.ftz.f32 %0, %1;" : "=f"(y) : "f"(x)); return y;
}
static __device__ __forceinline__ float lg2f(float x) {
    float y; asm("lg2.approx.f32 %0, %1;" : "=f"(y) : "f"(x)); return y;
}
static __device__ __forceinline__ unsigned long long pk2(float lo, float hi) {
    unsigned long long r;
    asm("mov.b64 %0, {%1, %2};" : "=l"(r) : "f"(lo), "f"(hi));
    return r;
}
static __device__ __forceinline__ void upk2(unsigned long long v, float& lo, float& hi) {
    asm("mov.b64 {%0, %1}, %2;" : "=f"(lo), "=f"(hi) : "l"(v));
}
// packed dual-FP32 FMA (Blackwell f32x2 pipe)
static __device__ __forceinline__ void fma2(unsigned long long& d,
                                            unsigned long long a,
                                            unsigned long long b) {
    asm("fma.rn.f32x2 %0, %1, %2, %0;" : "+l"(d) : "l"(a), "l"(b));
}
static __device__ __forceinline__ unsigned long long add2(unsigned long long a,
                                                          unsigned long long b) {
    unsigned long long d;
    asm("add.rn.f32x2 %0, %1, %2;" : "=l"(d) : "l"(a), "l"(b));
    return d;
}

// Dual 64-wide dot product (macro hygiene: internals underscore-prefixed;
// R10's NaN came from shadowing caller locals). Reads the broadcast 256B
// vector once (16 LDS.128); extracts state-0 value for the renormalizer.
#define MATVEC2(BUF, SUMA, SUMB, NORMV)                                        \
    do {                                                                       \
        const ulonglong2* _pd = reinterpret_cast<const ulonglong2*>(BUF);      \
        unsigned long long _aA0 = 0ull, _aA1 = 0ull, _aB0 = 0ull, _aB1 = 0ull; \
        _Pragma("unroll")                                                      \
        for (int _i = 0; _i < 16; _i++) {                                      \
            ulonglong2 _q = _pd[_i];                                           \
            if (_i == 0) { float _lo, _hi; upk2(_q.x, _lo, _hi); (NORMV) = _lo; } \
            fma2(_aA0, _q.x, EA[2 * _i]);                                      \
            fma2(_aB0, _q.x, EB[2 * _i]);                                      \
            fma2(_aA1, _q.y, EA[2 * _i + 1]);                                  \
            fma2(_aB1, _q.y, EB[2 * _i + 1]);                                  \
        }                                                                      \
        unsigned long long _s2A = add2(_aA0, _aA1);                            \
        unsigned long long _s2B = add2(_aB0, _aB1);                            \
        float _al, _ah, _bl, _bh;                                              \
        upk2(_s2A, _al, _ah);                                                  \
        upk2(_s2B, _bl, _bh);                                                  \
        (SUMA) = _al + _ah;                                                    \
        (SUMB) = _bl + _bh;                                                    \
    } while (0)

// Exact power-of-two renorm from state-0's exponent field; integer accumulate.
#define RENORM_I(NRM, RV)                                                      \
    const unsigned _nb = __float_as_uint(NRM);                                 \
    const int _ef = (int)(_nb >> 23);                                          \
    const float RV = __uint_as_float((unsigned)(254 - _ef) << 23);             \
    M2i += _ef;

// Forward step: emission applied AFTER the matvec. Rolling prefetch pointer,
// no clamp needed (max slice touched = mid + 4 <= 259 < T_LEN).
#define STEP_F(PE, P)                                                          \
    do {                                                                       \
        const float _Et0 = ex2f((PE).x * L2E);                                 \
        const float _Et1 = ex2f((PE).y * L2E);                                 \
        (PE) = __ldcs(prefp);                                                  \
        prefp += TSTR2;                                                        \
        *reinterpret_cast<float2*>(&psh[P][2 * lane]) = make_float2(a0, a1);   \
        __syncwarp();                                                          \
        float _sumA, _sumB, _nrm;                                              \
        MATVEC2(&psh[P][0], _sumA, _sumB, _nrm);                               \
        RENORM_I(_nrm, _r);                                                    \
        a0 = _sumA * (_Et0 * _r);                                              \
        a1 = _sumB * (_Et1 * _r);                                              \
    } while (0)

// Backward step: emission folded BEFORE the matvec; pointer clamped at t=0.
#define STEP_B(PE, P)                                                          \
    do {                                                                       \
        const float _c0 = a0 * ex2f((PE).x * L2E);                             \
        const float _c1 = a1 * ex2f((PE).y * L2E);                             \
        (PE) = __ldcs(prefp);                                                  \
        prefp = (prefp > pbase) ? (prefp - TSTR2) : pbase;                     \
        *reinterpret_cast<float2*>(&psh[P][2 * lane]) = make_float2(_c0, _c1); \
        __syncwarp();                                                          \
        float _sumA, _sumB, _nrm;                                              \
        MATVEC2(&psh[P][0], _sumA, _sumB, _nrm);                               \
        RENORM_I(_nrm, _r);                                                    \
        a0 = _sumA * _r;                                                       \
        a1 = _sumB * _r;                                                       \
    } while (0)

#define RUN_STEPS(STEP)                                                        \
    do {                                                                       \
        int _nq = nsteps >> 2;                                                 \
        const int _nr = nsteps & 3;                                            \
        while (_nq--) { STEP(p0, 1); STEP(p1, 0); STEP(p2, 1); STEP(p3, 0); }  \
        if (_nr) {                                                             \
            STEP(p0, 1);                                                       \
            if (_nr > 1) {                                                     \
                STEP(p1, 0);                                                   \
                if (_nr > 2) STEP(p2, 1);                                      \
            }                                                                  \
        }                                                                      \
    } while (0)

// One half-chain per 32-thread block (one warp). blk = 2*chain + dir.
//   dir 0: forward,  t = 1..mid   (+numerator terms for t <= mid, start bnd)
//   dir 1: backward, t = L-1..mid+1 (+numerator terms for t > mid, end bnd)
// Lane owns ADJACENT states 2*lane and 2*lane+1 (vector LDG.64/STS.64).
// The LAST of the two sibling blocks to finish fuses the combine.
// __launch_bounds__(32, 12): cap regs at 170 so 12 blocks fit per SM
// (R15 measured 210 regs -> only 9 resident -> 1.5 waves, packing 43%).
__global__ void __launch_bounds__(32, 12)
crf_half_kernel(const float* __restrict__ emis,    // (T,B,C,K)
                const int*   __restrict__ tags,    // (T,B,C)
                const int*   __restrict__ tok,     // (B,)
                const float* __restrict__ trans,   // (C,K,K)
                const float* __restrict__ startt,  // (C,K)
                const float* __restrict__ endt,    // (C,K)
                float*       __restrict__ out)     // (B,C)
{
    __shared__ __align__(16) float psh[2][K_SZ];

    const int blk   = blockIdx.x;
    const int dir   = blk & 1;
    const int chain = blk >> 1;
    const int b = chain >> 2;
    const int c = chain & 3;
    const int lane = threadIdx.x;
    const int s0 = 2 * lane;             // first owned state
    const unsigned FULL = 0xffffffffu;

    int L = tok[b];
    L = min(max(L, 1), T_LEN);
    const int mid = (L - 1) >> 1;

    const float* e0p = emis + ((size_t)b * C_SZ + c) * K_SZ;   // t=0 slice
    const float2* pbase = reinterpret_cast<const float2*>(e0p) + lane;
    const float* tr = trans + c * K_SZ * K_SZ;

    // ===== numerator partial for this dir (+boundary term on lane 0) =====
    float nacc = 0.f;
    {
        const int tlo = dir ? (mid + 1) : 1;
        const int thi = dir ? L : (mid + 1);
        for (int t = tlo + lane; t < thi; t += 32) {
            int tp = tags[((t - 1) * B_SZ + b) * C_SZ + c];
            int tc = tags[(t * B_SZ + b) * C_SZ + c];
            nacc += trans[(c * K_SZ + tp) * K_SZ + tc]
                  + emis[(((size_t)t * B_SZ + b) * C_SZ + c) * K_SZ + tc];
        }
        if (lane == 0) {
            if (dir == 0) {
                const int tag0 = tags[b * C_SZ + c];
                nacc += startt[c * K_SZ + tag0] + e0p[tag0];
            } else {
                const int tagL = tags[((L - 1) * B_SZ + b) * C_SZ + c];
                nacc += endt[c * K_SZ + tagL];
            }
        }
    }

    // ===== F registers =====
    // forward:  lane owns OUT states s0, s0+1 -> columns s0 / s0+1
    // backward: lane owns states s0, s0+1     -> rows s0 / s0+1
    unsigned long long EA[32], EB[32];
    if (dir == 0) {
        #pragma unroll
        for (int j = 0; j < 32; j++) {
            EA[j] = pk2(__expf(tr[(2 * j)     * K_SZ + s0]),
                        __expf(tr[(2 * j + 1) * K_SZ + s0]));
            EB[j] = pk2(__expf(tr[(2 * j)     * K_SZ + s0 + 1]),
                        __expf(tr[(2 * j + 1) * K_SZ + s0 + 1]));
        }
    } else {
        #pragma unroll
        for (int j = 0; j < 32; j++) {
            EA[j] = pk2(__expf(tr[s0 * K_SZ + 2 * j]),
                        __expf(tr[s0 * K_SZ + 2 * j + 1]));
            EB[j] = pk2(__expf(tr[(s0 + 1) * K_SZ + 2 * j]),
                        __expf(tr[(s0 + 1) * K_SZ + 2 * j + 1]));
        }
    }

    float a0, a1, m0;
    int M2i = 0;                       // biased exponent accumulator
    int nsteps;

    if (dir == 0) {
        nsteps = mid;

        // ---- forward init at t=0 ----
        const float2 e0v = pbase[0];
        const float2 st  = *reinterpret_cast<const float2*>(&startt[c * K_SZ + s0]);
        const float i0 = (st.x + e0v.x) * L2E;
        const float i1 = (st.y + e0v.y) * L2E;
        m0 = __shfl_sync(FULL, i0, 0);
        a0 = ex2f(i0 - m0);
        a1 = ex2f(i1 - m0);

        // prefill depth-4 ring (slices 1..4, always in-bounds)
        float2 p0 = __ldcs(pbase + 1 * TSTR2);
        float2 p1 = __ldcs(pbase + 2 * TSTR2);
        float2 p2 = __ldcs(pbase + 3 * TSTR2);
        float2 p3 = __ldcs(pbase + 4 * TSTR2);
        const float2* prefp = pbase + 5 * TSTR2;   // next prefetch slice

        RUN_STEPS(STEP_F);
    } else {
        nsteps = L - 1 - mid;

        // ---- backward init at t=L-1: b = exp(end) ----
        const float2 en = *reinterpret_cast<const float2*>(&endt[c * K_SZ + s0]);
        const float i0 = en.x * L2E;
        const float i1 = en.y * L2E;
        m0 = __shfl_sync(FULL, i0, 0);
        a0 = ex2f(i0 - m0);
        a1 = ex2f(i1 - m0);

        // prefill depth-4 ring (slices L-1 .. L-4, clamped at 0)
        float2 p0 = __ldcs(pbase + (size_t)max(L - 1, 0) * TSTR2);
        float2 p1 = __ldcs(pbase + (size_t)max(L - 2, 0) * TSTR2);
        float2 p2 = __ldcs(pbase + (size_t)max(L - 3, 0) * TSTR2);
        float2 p3 = __ldcs(pbase + (size_t)max(L - 4, 0) * TSTR2);
        const float2* prefp = pbase + (size_t)max(L - 5, 0) * TSTR2;

        RUN_STEPS(STEP_B);
    }

    // ===== numerator warp-reduce =====
    #pragma unroll
    for (int off = 16; off; off >>= 1)
        nacc += __shfl_xor_sync(FULL, nacc, off);

    // ===== publish the half-chain state =====
    reinterpret_cast<float2*>(&g_vec[blk][s0])[0] = make_float2(a0, a1);
    if (lane == 0) {
        g_m2[blk] = m0 + (float)(M2i - 127 * nsteps);
        g_np[blk] = nacc;
    }
    __threadfence();          // release: publishes visible before flag bump

    // ===== last-finisher fused combine (single warp, no barriers) =====
    int last = 0;
    if (lane == 0) last = atomicAdd(&g_flag[chain], 1);
    last = __shfl_sync(FULL, last, 0);

    if (last == 1) {
        __threadfence();      // acquire: partner's publishes visible
        const float2 af = reinterpret_cast<const float2*>(&g_vec[2 * chain][s0])[0];
        const float2 ab = reinterpret_cast<const float2*>(&g_vec[2 * chain + 1][s0])[0];
        float s = af.x * ab.x + af.y * ab.y;
        #pragma unroll
        for (int off = 16; off; off >>= 1)
            s += __shfl_xor_sync(FULL, s, off);
        if (lane == 0) {
            const float den = (g_m2[2 * chain] + g_m2[2 * chain + 1] + lg2f(s)) * LN2;
            out[chain] = g_np[2 * chain] + g_np[2 * chain + 1] - den;
            g_flag[chain] = 0;   // reset for next graph replay
        }
    }
}

extern "C" void kernel_launch(void* const* d_in, const int* in_sizes, int n_in,
                              void* d_out, int out_size) {
    const float* emis   = (const float*)d_in[0];
    const int*   tags   = (const int*)  d_in[1];
    const int*   tok    = (const int*)  d_in[2];
    const float* trans  = (const float*)d_in[3];
    const float* startt = (const float*)d_in[4];
    const float* endt   = (const float*)d_in[5];
    float* out = (float*)d_out;

    crf_half_kernel<<<2 * N_CHAIN, 32>>>(emis, tags, tok, trans, startt, endt, out);
}

// round 17
// speedup vs baseline: 1.2923x; 1.2923x over previous
#include <cuda_runtime.h>
#include <cstdint>

// Problem constants (fixed shapes)
#define T_LEN 512
#define B_SZ  256
#define C_SZ  4
#define K_SZ  64
#define L2E   1.4426950408889634f
#define LN2   0.6931471805599453f

#define N_CHAIN (B_SZ * C_SZ)                // 1024
#define TSTR2   ((B_SZ * C_SZ * K_SZ) / 2)   // time stride in float2 units

// Scratch for the forward/backward meet (allocation-free rule: device globals)
__device__ float g_vec[2 * N_CHAIN][K_SZ];   // [2*chain + dir][state]
__device__ float g_m2 [2 * N_CHAIN];         // log2 offsets
__device__ float g_np [2 * N_CHAIN];         // numerator partials (per dir)
__device__ int   g_flag[N_CHAIN];            // completion counters (zero-init)
__device__ int   g_perm[N_CHAIN];            // chains sorted by length desc

// ---------- small PTX helpers ----------
static __device__ __forceinline__ float ex2f(float x) {
    float y; asm("ex2.approx.ftz.f32 %0, %1;" : "=f"(y) : "f"(x)); return y;
}
static __device__ __forceinline__ float lg2f(float x) {
    float y; asm("lg2.approx.f32 %0, %1;" : "=f"(y) : "f"(x)); return y;
}
static __device__ __forceinline__ unsigned long long pk2(float lo, float hi) {
    unsigned long long r;
    asm("mov.b64 %0, {%1, %2};" : "=l"(r) : "f"(lo), "f"(hi));
    return r;
}
static __device__ __forceinline__ void upk2(unsigned long long v, float& lo, float& hi) {
    asm("mov.b64 {%0, %1}, %2;" : "=f"(lo), "=f"(hi) : "l"(v));
}
// packed dual-FP32 FMA (Blackwell f32x2 pipe)
static __device__ __forceinline__ void fma2(unsigned long long& d,
                                            unsigned long long a,
                                            unsigned long long b) {
    asm("fma.rn.f32x2 %0, %1, %2, %0;" : "+l"(d) : "l"(a), "l"(b));
}
static __device__ __forceinline__ unsigned long long add2(unsigned long long a,
                                                          unsigned long long b) {
    unsigned long long d;
    asm("add.rn.f32x2 %0, %1, %2;" : "=l"(d) : "l"(a), "l"(b));
    return d;
}

// Dual 64-wide dot product (macro hygiene: internals underscore-prefixed;
// R10's NaN came from shadowing caller locals). Reads the broadcast 256B
// vector once (16 LDS.128); extracts state-0 value for the renormalizer.
#define MATVEC2(BUF, SUMA, SUMB, NORMV)                                        \
    do {                                                                       \
        const ulonglong2* _pd = reinterpret_cast<const ulonglong2*>(BUF);      \
        unsigned long long _aA0 = 0ull, _aA1 = 0ull, _aB0 = 0ull, _aB1 = 0ull; \
        _Pragma("unroll")                                                      \
        for (int _i = 0; _i < 16; _i++) {                                      \
            ulonglong2 _q = _pd[_i];                                           \
            if (_i == 0) { float _lo, _hi; upk2(_q.x, _lo, _hi); (NORMV) = _lo; } \
            fma2(_aA0, _q.x, EA[2 * _i]);                                      \
            fma2(_aB0, _q.x, EB[2 * _i]);                                      \
            fma2(_aA1, _q.y, EA[2 * _i + 1]);                                  \
            fma2(_aB1, _q.y, EB[2 * _i + 1]);                                  \
        }                                                                      \
        unsigned long long _s2A = add2(_aA0, _aA1);                            \
        unsigned long long _s2B = add2(_aB0, _aB1);                            \
        float _al, _ah, _bl, _bh;                                              \
        upk2(_s2A, _al, _ah);                                                  \
        upk2(_s2B, _bl, _bh);                                                  \
        (SUMA) = _al + _ah;                                                    \
        (SUMB) = _bl + _bh;                                                    \
    } while (0)

// Exact power-of-two renorm from state-0's exponent field; integer accumulate.
#define RENORM_I(NRM, RV)                                                      \
    const unsigned _nb = __float_as_uint(NRM);                                 \
    const int _ef = (int)(_nb >> 23);                                          \
    const float RV = __uint_as_float((unsigned)(254 - _ef) << 23);             \
    M2i += _ef;

// Forward step: emission applied AFTER the matvec. Rolling prefetch pointer,
// no clamp needed (max slice touched = mid + 4 <= 259 < T_LEN).
#define STEP_F(PE, P)                                                          \
    do {                                                                       \
        const float _Et0 = ex2f((PE).x * L2E);                                 \
        const float _Et1 = ex2f((PE).y * L2E);                                 \
        (PE) = __ldcs(prefp);                                                  \
        prefp += TSTR2;                                                        \
        *reinterpret_cast<float2*>(&psh[P][2 * lane]) = make_float2(a0, a1);   \
        __syncwarp();                                                          \
        float _sumA, _sumB, _nrm;                                              \
        MATVEC2(&psh[P][0], _sumA, _sumB, _nrm);                               \
        RENORM_I(_nrm, _r);                                                    \
        a0 = _sumA * (_Et0 * _r);                                              \
        a1 = _sumB * (_Et1 * _r);                                              \
    } while (0)

// Backward step: emission folded BEFORE the matvec; pointer clamped at t=0.
#define STEP_B(PE, P)                                                          \
    do {                                                                       \
        const float _c0 = a0 * ex2f((PE).x * L2E);                             \
        const float _c1 = a1 * ex2f((PE).y * L2E);                             \
        (PE) = __ldcs(prefp);                                                  \
        prefp = (prefp > pbase) ? (prefp - TSTR2) : pbase;                     \
        *reinterpret_cast<float2*>(&psh[P][2 * lane]) = make_float2(_c0, _c1); \
        __syncwarp();                                                          \
        float _sumA, _sumB, _nrm;                                              \
        MATVEC2(&psh[P][0], _sumA, _sumB, _nrm);                               \
        RENORM_I(_nrm, _r);                                                    \
        a0 = _sumA * _r;                                                       \
        a1 = _sumB * _r;                                                       \
    } while (0)

#define RUN_STEPS(STEP)                                                        \
    do {                                                                       \
        int _nq = nsteps >> 2;                                                 \
        const int _nr = nsteps & 3;                                            \
        while (_nq--) { STEP(p0, 1); STEP(p1, 0); STEP(p2, 1); STEP(p3, 0); }  \
        if (_nr) {                                                             \
            STEP(p0, 1);                                                       \
            if (_nr > 1) {                                                     \
                STEP(p1, 0);                                                   \
                if (_nr > 2) STEP(p2, 1);                                      \
            }                                                                  \
        }                                                                      \
    } while (0)

// Pre-kernel: counting-sort the 1024 chains by token length, DESCENDING,
// into g_perm. Longest chains get the lowest block indices -> dispatched
// first -> LPT schedule, short chains backfill the tail.
// Tie order within a length bucket is atomic-race-dependent but harmless:
// chains are independent and per-chain results don't depend on schedule.
__global__ void __launch_bounds__(N_CHAIN)
crf_order_kernel(const int* __restrict__ tok)
{
    __shared__ int hist[T_LEN + 1];
    __shared__ int base[T_LEN + 1];
    const int tid = threadIdx.x;

    if (tid <= T_LEN) hist[tid] = 0;
    __syncthreads();

    int L = tok[tid >> 2];
    L = min(max(L, 1), T_LEN);
    atomicAdd(&hist[L], 1);
    __syncthreads();

    if (tid == 0) {
        int acc = 0;
        for (int k = T_LEN; k >= 1; k--) { base[k] = acc; acc += hist[k]; }
    }
    __syncthreads();
    if (tid <= T_LEN) hist[tid] = 0;
    __syncthreads();

    const int pos = base[L] + atomicAdd(&hist[L], 1);
    g_perm[pos] = tid;
}

// One half-chain per 32-thread block (one warp). blk = 2*slot + dir,
// chain = g_perm[slot] (longest first).
//   dir 0: forward,  t = 1..mid   (+numerator terms for t <= mid, start bnd)
//   dir 1: backward, t = L-1..mid+1 (+numerator terms for t > mid, end bnd)
// Lane owns ADJACENT states 2*lane and 2*lane+1 (vector LDG.64/STS.64).
// The LAST of the two sibling blocks to finish fuses the combine.
__global__ void __launch_bounds__(32)
crf_half_kernel(const float* __restrict__ emis,    // (T,B,C,K)
                const int*   __restrict__ tags,    // (T,B,C)
                const int*   __restrict__ tok,     // (B,)
                const float* __restrict__ trans,   // (C,K,K)
                const float* __restrict__ startt,  // (C,K)
                const float* __restrict__ endt,    // (C,K)
                float*       __restrict__ out)     // (B,C)
{
    __shared__ __align__(16) float psh[2][K_SZ];

    const int blk   = blockIdx.x;
    const int dir   = blk & 1;
    const int chain = g_perm[blk >> 1];
    const int b = chain >> 2;
    const int c = chain & 3;
    const int lane = threadIdx.x;
    const int s0 = 2 * lane;             // first owned state
    const unsigned FULL = 0xffffffffu;

    int L = tok[b];
    L = min(max(L, 1), T_LEN);
    const int mid = (L - 1) >> 1;

    const float* e0p = emis + ((size_t)b * C_SZ + c) * K_SZ;   // t=0 slice
    const float2* pbase = reinterpret_cast<const float2*>(e0p) + lane;
    const float* tr = trans + c * K_SZ * K_SZ;

    // ===== numerator partial for this dir (+boundary term on lane 0) =====
    float nacc = 0.f;
    {
        const int tlo = dir ? (mid + 1) : 1;
        const int thi = dir ? L : (mid + 1);
        for (int t = tlo + lane; t < thi; t += 32) {
            int tp = tags[((t - 1) * B_SZ + b) * C_SZ + c];
            int tc = tags[(t * B_SZ + b) * C_SZ + c];
            nacc += trans[(c * K_SZ + tp) * K_SZ + tc]
                  + emis[(((size_t)t * B_SZ + b) * C_SZ + c) * K_SZ + tc];
        }
        if (lane == 0) {
            if (dir == 0) {
                const int tag0 = tags[b * C_SZ + c];
                nacc += startt[c * K_SZ + tag0] + e0p[tag0];
            } else {
                const int tagL = tags[((L - 1) * B_SZ + b) * C_SZ + c];
                nacc += endt[c * K_SZ + tagL];
            }
        }
    }

    // ===== F registers =====
    // forward:  lane owns OUT states s0, s0+1 -> columns s0 / s0+1
    // backward: lane owns states s0, s0+1     -> rows s0 / s0+1
    unsigned long long EA[32], EB[32];
    if (dir == 0) {
        #pragma unroll
        for (int j = 0; j < 32; j++) {
            EA[j] = pk2(__expf(tr[(2 * j)     * K_SZ + s0]),
                        __expf(tr[(2 * j + 1) * K_SZ + s0]));
            EB[j] = pk2(__expf(tr[(2 * j)     * K_SZ + s0 + 1]),
                        __expf(tr[(2 * j + 1) * K_SZ + s0 + 1]));
        }
    } else {
        #pragma unroll
        for (int j = 0; j < 32; j++) {
            EA[j] = pk2(__expf(tr[s0 * K_SZ + 2 * j]),
                        __expf(tr[s0 * K_SZ + 2 * j + 1]));
            EB[j] = pk2(__expf(tr[(s0 + 1) * K_SZ + 2 * j]),
                        __expf(tr[(s0 + 1) * K_SZ + 2 * j + 1]));
        }
    }

    float a0, a1, m0;
    int M2i = 0;                       // biased exponent accumulator
    int nsteps;

    if (dir == 0) {
        nsteps = mid;

        // ---- forward init at t=0 ----
        const float2 e0v = pbase[0];
        const float2 st  = *reinterpret_cast<const float2*>(&startt[c * K_SZ + s0]);
        const float i0 = (st.x + e0v.x) * L2E;
        const float i1 = (st.y + e0v.y) * L2E;
        m0 = __shfl_sync(FULL, i0, 0);
        a0 = ex2f(i0 - m0);
        a1 = ex2f(i1 - m0);

        // prefill depth-4 ring (slices 1..4, always in-bounds)
        float2 p0 = __ldcs(pbase + 1 * TSTR2);
        float2 p1 = __ldcs(pbase + 2 * TSTR2);
        float2 p2 = __ldcs(pbase + 3 * TSTR2);
        float2 p3 = __ldcs(pbase + 4 * TSTR2);
        const float2* prefp = pbase + 5 * TSTR2;   // next prefetch slice

        RUN_STEPS(STEP_F);
    } else {
        nsteps = L - 1 - mid;

        // ---- backward init at t=L-1: b = exp(end) ----
        const float2 en = *reinterpret_cast<const float2*>(&endt[c * K_SZ + s0]);
        const float i0 = en.x * L2E;
        const float i1 = en.y * L2E;
        m0 = __shfl_sync(FULL, i0, 0);
        a0 = ex2f(i0 - m0);
        a1 = ex2f(i1 - m0);

        // prefill depth-4 ring (slices L-1 .. L-4, clamped at 0)
        float2 p0 = __ldcs(pbase + (size_t)max(L - 1, 0) * TSTR2);
        float2 p1 = __ldcs(pbase + (size_t)max(L - 2, 0) * TSTR2);
        float2 p2 = __ldcs(pbase + (size_t)max(L - 3, 0) * TSTR2);
        float2 p3 = __ldcs(pbase + (size_t)max(L - 4, 0) * TSTR2);
        const float2* prefp = pbase + (size_t)max(L - 5, 0) * TSTR2;

        RUN_STEPS(STEP_B);
    }

    // ===== numerator warp-reduce =====
    #pragma unroll
    for (int off = 16; off; off >>= 1)
        nacc += __shfl_xor_sync(FULL, nacc, off);

    // ===== publish the half-chain state =====
    reinterpret_cast<float2*>(&g_vec[2 * chain + dir][s0])[0] = make_float2(a0, a1);
    if (lane == 0) {
        g_m2[2 * chain + dir] = m0 + (float)(M2i - 127 * nsteps);
        g_np[2 * chain + dir] = nacc;
    }
    __threadfence();          // release: publishes visible before flag bump

    // ===== last-finisher fused combine (single warp, no barriers) =====
    int last = 0;
    if (lane == 0) last = atomicAdd(&g_flag[chain], 1);
    last = __shfl_sync(FULL, last, 0);

    if (last == 1) {
        __threadfence();      // acquire: partner's publishes visible
        const float2 af = reinterpret_cast<const float2*>(&g_vec[2 * chain][s0])[0];
        const float2 ab = reinterpret_cast<const float2*>(&g_vec[2 * chain + 1][s0])[0];
        float s = af.x * ab.x + af.y * ab.y;
        #pragma unroll
        for (int off = 16; off; off >>= 1)
            s += __shfl_xor_sync(FULL, s, off);
        if (lane == 0) {
            const float den = (g_m2[2 * chain] + g_m2[2 * chain + 1] + lg2f(s)) * LN2;
            out[chain] = g_np[2 * chain] + g_np[2 * chain + 1] - den;
            g_flag[chain] = 0;   // reset for next graph replay
        }
    }
}

extern "C" void kernel_launch(void* const* d_in, const int* in_sizes, int n_in,
                              void* d_out, int out_size) {
    const float* emis   = (const float*)d_in[0];
    const int*   tags   = (const int*)  d_in[1];
    const int*   tok    = (const int*)  d_in[2];
    const float* trans  = (const float*)d_in[3];
    const float* startt = (const float*)d_in[4];
    const float* endt   = (const float*)d_in[5];
    float* out = (float*)d_out;

    crf_order_kernel<<<1, N_CHAIN>>>(tok);
    crf_half_kernel<<<2 * N_CHAIN, 32>>>(emis, tags, tok, trans, startt, endt, out);
}